// round 10
// baseline (speedup 1.0000x reference)
#include <cuda_runtime.h>
#include <cuda_bf16.h>
#include <cuda_fp16.h>
#include <cuda_fp8.h>
#include <math.h>
#include <stdint.h>

#define T_ 512
#define D_ 2048
#define I_ 768
#define E_ 16
#define K_ 8

// ---------------- helpers ----------------
__device__ __forceinline__ uint32_t smem_u32(const void* p) {
    uint32_t a;
    asm("{ .reg .u64 t; cvta.to.shared.u64 t, %1; cvt.u32.u64 %0, t; }" : "=r"(a) : "l"(p));
    return a;
}
__device__ __forceinline__ void ldm_x4(uint32_t* r, uint32_t addr) {
    asm volatile("ldmatrix.sync.aligned.m8n8.x4.shared.b16 {%0,%1,%2,%3}, [%4];"
        : "=r"(r[0]), "=r"(r[1]), "=r"(r[2]), "=r"(r[3]) : "r"(addr));
}
__device__ __forceinline__ void mma_bf16(float* c, const uint32_t* a, const uint32_t* b) {
    asm volatile("mma.sync.aligned.m16n8k16.row.col.f32.bf16.bf16.f32 "
        "{%0,%1,%2,%3}, {%4,%5,%6,%7}, {%8,%9}, {%0,%1,%2,%3};"
        : "+f"(c[0]), "+f"(c[1]), "+f"(c[2]), "+f"(c[3])
        : "r"(a[0]), "r"(a[1]), "r"(a[2]), "r"(a[3]), "r"(b[0]), "r"(b[1]));
}
__device__ __forceinline__ void mma_f16(float* c, const uint32_t* a, const uint32_t* b) {
    asm volatile("mma.sync.aligned.m16n8k16.row.col.f32.f16.f16.f32 "
        "{%0,%1,%2,%3}, {%4,%5,%6,%7}, {%8,%9}, {%0,%1,%2,%3};"
        : "+f"(c[0]), "+f"(c[1]), "+f"(c[2]), "+f"(c[3])
        : "r"(a[0]), "r"(a[1]), "r"(a[2]), "r"(a[3]), "r"(b[0]), "r"(b[1]));
}

// ---------------- scratch ----------------
__device__ __nv_bfloat16 g_xb[T_ * D_];   // quant-dequantized activations (exact bf16)
__device__ __half g_ah[E_ * T_ * I_];     // activation a/64 in fp16
__device__ int   g_tok[E_ * T_];
__device__ int   g_cnt[E_];
__device__ float g_comb[T_ * E_];
__device__ int   g_flag[T_ * E_];

__constant__ float c_fp4[16] = {0.0f, 0.5f, 1.0f, 1.5f, 2.0f, 3.0f, 4.0f, 6.0f,
                                -0.0f, -0.5f, -1.0f, -1.5f, -2.0f, -3.0f, -4.0f, -6.0f};

// ---------------- fused preamble: zero out + fp8 quant-dequant + routing ----------------
__global__ void prep_kernel(const float* __restrict__ x,
                            const float* __restrict__ tw,
                            const int* __restrict__ tids,
                            float* __restrict__ out) {
    const int i = blockIdx.x * blockDim.x + threadIdx.x;
    if (i < T_ * D_) out[i] = 0.0f;

    {
        int g = i >> 5, lane = i & 31;
        if (g < (T_ * D_) / 32) {
            float v = x[g * 32 + lane];
            float av = fabsf(v);
            #pragma unroll
            for (int o = 16; o; o >>= 1) av = fmaxf(av, __shfl_xor_sync(0xffffffffu, av, o));
            av = fmaxf(av, 1e-4f);
            float scale = av / 448.0f;
            unsigned bits = __float_as_uint(scale);
            unsigned exp = ((bits >> 23) & 255u) + ((bits & 0x7fffffu) ? 1u : 0u);
            exp = min(max(exp, 1u), 254u);
            float rscale = __uint_as_float(exp << 23);
            float inv = 1.0f / rscale;
            __nv_fp8_storage_t q = __nv_cvt_float_to_fp8(v * inv, __NV_SATFINITE, __NV_E4M3);
            float qf = __half2float(__half(__nv_cvt_fp8_to_halfraw(q, __NV_E4M3)));
            g_xb[g * 32 + lane] = __float2bfloat16(qf * rscale);
        }
    }

    if (i < T_) {
        int ids[K_]; float w[K_];
        #pragma unroll
        for (int k = 0; k < K_; k++) { ids[k] = tids[i * K_ + k]; w[k] = tw[i * K_ + k]; }
        #pragma unroll
        for (int e = 0; e < E_; e++) {
            float s = 0.0f; int f = 0;
            #pragma unroll
            for (int k = 0; k < K_; k++)
                if (ids[k] == e) { s += w[k]; f = 1; }
            g_comb[i * E_ + e] = s;
            g_flag[i * E_ + e] = f;
        }
    }
}

__global__ void route_compact_par() {
    __shared__ int s[T_];
    const int e = blockIdx.x;
    const int t = threadIdx.x;
    int f = g_flag[t * E_ + e];
    s[t] = f;
    __syncthreads();
    #pragma unroll
    for (int off = 1; off < T_; off <<= 1) {
        int v = (t >= off) ? s[t - off] : 0;
        __syncthreads();
        s[t] += v;
        __syncthreads();
    }
    if (f) g_tok[e * T_ + s[t] - 1] = t;
    if (t == T_ - 1) g_cnt[e] = s[t];
}

// fp4 byte (2 nibbles) -> packed bf16x2 / f16x2, scaled
__device__ __forceinline__ uint32_t dq2(int w, float s, const float* tab) {
    float lo = tab[w & 15] * s;
    float hi = tab[(w >> 4) & 15] * s;
    __nv_bfloat162 h = __floats2bfloat162_rn(lo, hi);
    return *reinterpret_cast<uint32_t*>(&h);
}
__device__ __forceinline__ uint32_t dq2h(int w, float s, const float* tab) {
    float lo = tab[w & 15] * s;
    float hi = tab[(w >> 4) & 15] * s;
    __half2 h = __floats2half2_rn(lo, hi);
    return *reinterpret_cast<uint32_t*>(&h);
}
__device__ __forceinline__ uint4 dq8(int4 w, float s, const float* tab) {
    uint4 o;
    o.x = dq2(w.x, s, tab); o.y = dq2(w.y, s, tab);
    o.z = dq2(w.z, s, tab); o.w = dq2(w.w, s, tab);
    return o;
}
__device__ __forceinline__ uint4 dq8h(int4 w, float s, const float* tab) {
    uint4 o;
    o.x = dq2h(w.x, s, tab); o.y = dq2h(w.y, s, tab);
    o.z = dq2h(w.z, s, tab); o.w = dq2h(w.w, s, tab);
    return o;
}

#define RS2 80                         // 32 elems x 2B + 16B pad (conflict-free ldmatrix)
#define STG1 (64 * RS2 + 64 * RS2)     // gemm1 stage: A(64 rows) + G(32) + U(32)
#define STG2 (64 * RS2 + 64 * RS2)     // gemm2 stage: A(64) + B(64)

// ================= GEMM1: h = x @ w13^T, a = silu(g)*u  (bf16, ping-pong BK=32) =================
// block: 128 thr, tile m64 x (G32 + U32); warps 2m x 2n; warp 32m x (16G + 16U)
__global__ void __launch_bounds__(128, 5)
gemm1_kernel(const int* __restrict__ w13, const int* __restrict__ w13s) {
    const int e = blockIdx.z;
    const int cnt = g_cnt[e];
    const int m0 = blockIdx.y * 64;
    if (m0 >= cnt) return;
    const int n0 = blockIdx.x * 32;

    __shared__ __align__(16) unsigned char sm[2 * STG1];
    __shared__ float tab[16];
    __shared__ int toks[64];

    const int tid = threadIdx.x, wid = tid >> 5, lid = tid & 31;
    if (tid < 16) tab[tid] = c_fp4[tid];
    if (tid < 64) toks[tid] = g_tok[e * T_ + min(m0 + tid, cnt - 1)];
    __syncthreads();

    const int* we = w13 + (size_t)e * (2 * I_) * (D_ / 2);
    const int* se = w13s + (size_t)e * (2 * I_) * (D_ / 32);
    const uint32_t smB = smem_u32(sm);
    const int wm = wid >> 1, wn = wid & 1;

    // A coords: 64 rows x 4 segs(16B); each thread covers 2 adjacent segs (32B)
    const int car = tid >> 1, cas = (tid & 1) * 2;
    const size_t asrc = (size_t)toks[car] * D_ + cas * 8;
    const uint32_t adst = car * RS2 + cas * 16;
    // B coords: 2 per thread; row 0..63 (G 0-31, U 32-63), seg 0..3 (8 elems each)
    int brow[2], bseg[2]; size_t bw_off[2], bs_off[2]; uint32_t bdst[2];
    #pragma unroll
    for (int r = 0; r < 2; r++) {
        int j = tid + r * 128;
        brow[r] = j >> 2; bseg[r] = j & 3;
        int f = (brow[r] < 32) ? (n0 + brow[r]) : (I_ + n0 + brow[r] - 32);
        bw_off[r] = (size_t)f * (D_ / 2) + bseg[r] * 4;
        bs_off[r] = (size_t)f * (D_ / 32);
        bdst[r] = ((brow[r] < 32) ? (64 * RS2 + brow[r] * RS2) : (96 * RS2 + (brow[r] - 32) * RS2))
                  + bseg[r] * 16;
    }

    float cg[2][2][4] = {};
    float cu[2][2][4] = {};

    uint4 pa[2]; int4 pw[2]; float ps[2];
    // prologue: chunk 0 -> stage 0
    pa[0] = *(const uint4*)&g_xb[asrc];
    pa[1] = *(const uint4*)&g_xb[asrc + 8];
    #pragma unroll
    for (int r = 0; r < 2; r++) {
        pw[r] = *(const int4*)&we[bw_off[r]];
        ps[r] = __uint_as_float((unsigned)se[bs_off[r]] << 23);
    }
    *(uint4*)(sm + adst) = pa[0];
    *(uint4*)(sm + adst + 16) = pa[1];
    #pragma unroll
    for (int r = 0; r < 2; r++) *(uint4*)(sm + bdst[r]) = dq8(pw[r], ps[r], tab);
    // prefetch chunk 1
    pa[0] = *(const uint4*)&g_xb[asrc + 32];
    pa[1] = *(const uint4*)&g_xb[asrc + 40];
    #pragma unroll
    for (int r = 0; r < 2; r++) {
        pw[r] = *(const int4*)&we[bw_off[r] + 16];
        ps[r] = __uint_as_float((unsigned)se[bs_off[r] + 1] << 23);
    }
    __syncthreads();

    const int NC = D_ / 32;
    for (int c = 0; c < NC; c++) {
        const uint32_t sb = smB + (c & 1) * STG1;
        // MMA on stage c&1
        #pragma unroll
        for (int kk = 0; kk < 2; kk++) {
            uint32_t af[2][4];
            #pragma unroll
            for (int mf = 0; mf < 2; mf++)
                ldm_x4(af[mf], sb + (wm * 32 + mf * 16 + (lid & 15)) * RS2 + kk * 32 + (lid >> 4) * 16);
            const int nrow_off = ((lid >> 4) << 3) + (lid & 7);
            const int bcol = kk * 32 + ((lid >> 3) & 1) * 16;
            uint32_t bg[4], bu[4];
            ldm_x4(bg, sb + 64 * RS2 + (wn * 16 + nrow_off) * RS2 + bcol);
            ldm_x4(bu, sb + 96 * RS2 + (wn * 16 + nrow_off) * RS2 + bcol);
            #pragma unroll
            for (int mf = 0; mf < 2; mf++)
                #pragma unroll
                for (int sub = 0; sub < 2; sub++) {
                    mma_bf16(cg[mf][sub], af[mf], &bg[sub * 2]);
                    mma_bf16(cu[mf][sub], af[mf], &bu[sub * 2]);
                }
        }
        // store prefetched chunk c+1 into the other stage (safe: its readers passed last barrier)
        if (c + 1 < NC) {
            unsigned char* so = sm + ((c + 1) & 1) * STG1;
            *(uint4*)(so + adst) = pa[0];
            *(uint4*)(so + adst + 16) = pa[1];
            #pragma unroll
            for (int r = 0; r < 2; r++) *(uint4*)(so + bdst[r]) = dq8(pw[r], ps[r], tab);
        }
        __syncthreads();
        // prefetch chunk c+2 (covered by next chunk's MMA phase)
        if (c + 2 < NC) {
            const int k0 = (c + 2) * 32;
            pa[0] = *(const uint4*)&g_xb[asrc + k0];
            pa[1] = *(const uint4*)&g_xb[asrc + k0 + 8];
            #pragma unroll
            for (int r = 0; r < 2; r++) {
                pw[r] = *(const int4*)&we[bw_off[r] + (k0 >> 1)];
                ps[r] = __uint_as_float((unsigned)se[bs_off[r] + (k0 >> 5)] << 23);
            }
        }
    }

    // epilogue: a = silu(g)*u, store a/64 as fp16
    #pragma unroll
    for (int mf = 0; mf < 2; mf++) {
        #pragma unroll
        for (int half = 0; half < 2; half++) {
            int m = m0 + wm * 32 + mf * 16 + (lid >> 2) + half * 8;
            if (m < cnt) {
                size_t rowp = ((size_t)e * T_ + m) * I_ + n0;
                #pragma unroll
                for (int sub = 0; sub < 2; sub++) {
                    float g0 = cg[mf][sub][half * 2 + 0], g1 = cg[mf][sub][half * 2 + 1];
                    float u0 = cu[mf][sub][half * 2 + 0], u1 = cu[mf][sub][half * 2 + 1];
                    float a0 = g0 * u0 / (1.0f + __expf(-g0)) * 0.015625f;
                    float a1 = g1 * u1 / (1.0f + __expf(-g1)) * 0.015625f;
                    int col = wn * 16 + sub * 8 + (lid & 3) * 2;
                    __half2 h2 = __floats2half2_rn(a0, a1);
                    *(uint32_t*)&g_ah[rowp + col] = *(uint32_t*)&h2;
                }
            }
        }
    }
}

// ================= GEMM2: out += (64*comb) * ((a/64) @ w2^T)  (fp16, ping-pong BK=32) =================
// block: 128 thr, tile m64 x n64; warps 2m x 2n; warp 32 x 32
__global__ void __launch_bounds__(128, 5)
gemm2_kernel(const int* __restrict__ w2, const int* __restrict__ w2s, float* __restrict__ out) {
    const int e = blockIdx.z;
    const int cnt = g_cnt[e];
    const int m0 = blockIdx.y * 64;
    if (m0 >= cnt) return;
    const int n0 = blockIdx.x * 64;

    __shared__ __align__(16) unsigned char sm[2 * STG2];
    __shared__ float tab[16];
    __shared__ int toks[64];

    const int tid = threadIdx.x, wid = tid >> 5, lid = tid & 31;
    if (tid < 16) tab[tid] = c_fp4[tid];
    if (tid < 64) toks[tid] = g_tok[e * T_ + min(m0 + tid, cnt - 1)];
    __syncthreads();

    const int* we = w2 + (size_t)e * D_ * (I_ / 2);
    const int* se = w2s + (size_t)e * D_ * (I_ / 32);
    const uint32_t smB = smem_u32(sm);
    const int wm = wid >> 1, wn = wid & 1;

    const int car = tid >> 1, cas = (tid & 1) * 2;
    const size_t asrc = ((size_t)e * T_ + m0 + car) * I_ + cas * 8;
    const uint32_t adst = car * RS2 + cas * 16;
    int brow[2], bseg[2]; size_t bw_off[2], bs_off[2]; uint32_t bdst[2];
    #pragma unroll
    for (int r = 0; r < 2; r++) {
        int j = tid + r * 128;
        brow[r] = j >> 2; bseg[r] = j & 3;
        int f = n0 + brow[r];
        bw_off[r] = (size_t)f * (I_ / 2) + bseg[r] * 4;
        bs_off[r] = (size_t)f * (I_ / 32);
        bdst[r] = 64 * RS2 + brow[r] * RS2 + bseg[r] * 16;
    }

    float acc[2][4][4] = {};

    uint4 pa[2]; int4 pw[2]; float ps[2];
    pa[0] = *(const uint4*)&g_ah[asrc];
    pa[1] = *(const uint4*)&g_ah[asrc + 8];
    #pragma unroll
    for (int r = 0; r < 2; r++) {
        pw[r] = *(const int4*)&we[bw_off[r]];
        ps[r] = __uint_as_float((unsigned)se[bs_off[r]] << 23);
    }
    *(uint4*)(sm + adst) = pa[0];
    *(uint4*)(sm + adst + 16) = pa[1];
    #pragma unroll
    for (int r = 0; r < 2; r++) *(uint4*)(sm + bdst[r]) = dq8h(pw[r], ps[r], tab);
    pa[0] = *(const uint4*)&g_ah[asrc + 32];
    pa[1] = *(const uint4*)&g_ah[asrc + 40];
    #pragma unroll
    for (int r = 0; r < 2; r++) {
        pw[r] = *(const int4*)&we[bw_off[r] + 16];
        ps[r] = __uint_as_float((unsigned)se[bs_off[r] + 1] << 23);
    }
    __syncthreads();

    const int NC = I_ / 32;
    for (int c = 0; c < NC; c++) {
        const uint32_t sb = smB + (c & 1) * STG2;
        #pragma unroll
        for (int kk = 0; kk < 2; kk++) {
            uint32_t af[2][4];
            #pragma unroll
            for (int mf = 0; mf < 2; mf++)
                ldm_x4(af[mf], sb + (wm * 32 + mf * 16 + (lid & 15)) * RS2 + kk * 32 + (lid >> 4) * 16);
            const int nrow_off = ((lid >> 4) << 3) + (lid & 7);
            const int bcol = kk * 32 + ((lid >> 3) & 1) * 16;
            #pragma unroll
            for (int ng = 0; ng < 2; ng++) {
                uint32_t bb[4];
                ldm_x4(bb, sb + 64 * RS2 + (wn * 32 + ng * 16 + nrow_off) * RS2 + bcol);
                #pragma unroll
                for (int mf = 0; mf < 2; mf++)
                    #pragma unroll
                    for (int sub = 0; sub < 2; sub++)
                        mma_f16(acc[mf][ng * 2 + sub], af[mf], &bb[sub * 2]);
            }
        }
        if (c + 1 < NC) {
            unsigned char* so = sm + ((c + 1) & 1) * STG2;
            *(uint4*)(so + adst) = pa[0];
            *(uint4*)(so + adst + 16) = pa[1];
            #pragma unroll
            for (int r = 0; r < 2; r++) *(uint4*)(so + bdst[r]) = dq8h(pw[r], ps[r], tab);
        }
        __syncthreads();
        if (c + 2 < NC) {
            const int k0 = (c + 2) * 32;
            pa[0] = *(const uint4*)&g_ah[asrc + k0];
            pa[1] = *(const uint4*)&g_ah[asrc + k0 + 8];
            #pragma unroll
            for (int r = 0; r < 2; r++) {
                pw[r] = *(const int4*)&we[bw_off[r] + (k0 >> 1)];
                ps[r] = __uint_as_float((unsigned)se[bs_off[r] + (k0 >> 5)] << 23);
            }
        }
    }

    // epilogue: weighted scatter (comb * 64 compensates a/64)
    #pragma unroll
    for (int mf = 0; mf < 2; mf++) {
        #pragma unroll
        for (int half = 0; half < 2; half++) {
            int mrow = wm * 32 + mf * 16 + (lid >> 2) + half * 8;
            int m = m0 + mrow;
            if (m < cnt) {
                int t = toks[mrow];
                float cw = g_comb[t * E_ + e] * 64.0f;
                float* orow = out + (size_t)t * D_ + n0;
                #pragma unroll
                for (int nf = 0; nf < 4; nf++) {
                    int col = wn * 32 + nf * 8 + (lid & 3) * 2;
                    atomicAdd(&orow[col],     cw * acc[mf][nf][half * 2 + 0]);
                    atomicAdd(&orow[col + 1], cw * acc[mf][nf][half * 2 + 1]);
                }
            }
        }
    }
}

// ---------------- launch ----------------
extern "C" void kernel_launch(void* const* d_in, const int* in_sizes, int n_in,
                              void* d_out, int out_size) {
    const float* hs   = (const float*)d_in[0];
    const float* tw   = (const float*)d_in[1];
    const int*   tids = (const int*)d_in[2];
    const int*   w13  = (const int*)d_in[3];
    const int*   w13s = (const int*)d_in[4];
    const int*   w2   = (const int*)d_in[5];
    const int*   w2s  = (const int*)d_in[6];
    float* out = (float*)d_out;

    prep_kernel<<<(T_ * D_ + 255) / 256, 256>>>(hs, tw, tids, out);
    route_compact_par<<<E_, T_>>>();

    dim3 g1(I_ / 32, T_ / 64, E_);    // 24 x 8 x 16
    gemm1_kernel<<<g1, 128>>>(w13, w13s);

    dim3 g2(D_ / 64, T_ / 64, E_);    // 32 x 8 x 16
    gemm2_kernel<<<g2, 128>>>(w2, w2s, out);
}

// round 11
// speedup vs baseline: 1.0485x; 1.0485x over previous
#include <cuda_runtime.h>
#include <cuda_bf16.h>
#include <cuda_fp16.h>
#include <cuda_fp8.h>
#include <math.h>
#include <stdint.h>

#define T_ 512
#define D_ 2048
#define I_ 768
#define E_ 16
#define K_ 8

// ---------------- helpers ----------------
__device__ __forceinline__ uint32_t smem_u32(const void* p) {
    uint32_t a;
    asm("{ .reg .u64 t; cvta.to.shared.u64 t, %1; cvt.u32.u64 %0, t; }" : "=r"(a) : "l"(p));
    return a;
}
__device__ __forceinline__ void ldm_x4(uint32_t* r, uint32_t addr) {
    asm volatile("ldmatrix.sync.aligned.m8n8.x4.shared.b16 {%0,%1,%2,%3}, [%4];"
        : "=r"(r[0]), "=r"(r[1]), "=r"(r[2]), "=r"(r[3]) : "r"(addr));
}
__device__ __forceinline__ void mma_bf16(float* c, const uint32_t* a, const uint32_t* b) {
    asm volatile("mma.sync.aligned.m16n8k16.row.col.f32.bf16.bf16.f32 "
        "{%0,%1,%2,%3}, {%4,%5,%6,%7}, {%8,%9}, {%0,%1,%2,%3};"
        : "+f"(c[0]), "+f"(c[1]), "+f"(c[2]), "+f"(c[3])
        : "r"(a[0]), "r"(a[1]), "r"(a[2]), "r"(a[3]), "r"(b[0]), "r"(b[1]));
}
__device__ __forceinline__ void mma_f16(float* c, const uint32_t* a, const uint32_t* b) {
    asm volatile("mma.sync.aligned.m16n8k16.row.col.f32.f16.f16.f32 "
        "{%0,%1,%2,%3}, {%4,%5,%6,%7}, {%8,%9}, {%0,%1,%2,%3};"
        : "+f"(c[0]), "+f"(c[1]), "+f"(c[2]), "+f"(c[3])
        : "r"(a[0]), "r"(a[1]), "r"(a[2]), "r"(a[3]), "r"(b[0]), "r"(b[1]));
}

// ---------------- scratch ----------------
__device__ __nv_bfloat16 g_xb[T_ * D_];   // quant-dequantized activations (exact bf16)
__device__ __half g_ah[E_ * T_ * I_];     // activation a/64 in fp16
__device__ int   g_tok[E_ * T_];
__device__ int   g_cnt[E_];
__device__ float g_comb[T_ * E_];
__device__ int   g_flag[T_ * E_];

__constant__ float c_fp4[16] = {0.0f, 0.5f, 1.0f, 1.5f, 2.0f, 3.0f, 4.0f, 6.0f,
                                -0.0f, -0.5f, -1.0f, -1.5f, -2.0f, -3.0f, -4.0f, -6.0f};

// ---------------- fused preamble ----------------
__global__ void prep_kernel(const float* __restrict__ x,
                            const float* __restrict__ tw,
                            const int* __restrict__ tids,
                            float* __restrict__ out) {
    const int i = blockIdx.x * blockDim.x + threadIdx.x;
    if (i < T_ * D_) out[i] = 0.0f;

    {
        int g = i >> 5, lane = i & 31;
        if (g < (T_ * D_) / 32) {
            float v = x[g * 32 + lane];
            float av = fabsf(v);
            #pragma unroll
            for (int o = 16; o; o >>= 1) av = fmaxf(av, __shfl_xor_sync(0xffffffffu, av, o));
            av = fmaxf(av, 1e-4f);
            float scale = av / 448.0f;
            unsigned bits = __float_as_uint(scale);
            unsigned exp = ((bits >> 23) & 255u) + ((bits & 0x7fffffu) ? 1u : 0u);
            exp = min(max(exp, 1u), 254u);
            float rscale = __uint_as_float(exp << 23);
            float inv = 1.0f / rscale;
            __nv_fp8_storage_t q = __nv_cvt_float_to_fp8(v * inv, __NV_SATFINITE, __NV_E4M3);
            float qf = __half2float(__half(__nv_cvt_fp8_to_halfraw(q, __NV_E4M3)));
            g_xb[g * 32 + lane] = __float2bfloat16(qf * rscale);
        }
    }

    if (i < T_) {
        int ids[K_]; float w[K_];
        #pragma unroll
        for (int k = 0; k < K_; k++) { ids[k] = tids[i * K_ + k]; w[k] = tw[i * K_ + k]; }
        #pragma unroll
        for (int e = 0; e < E_; e++) {
            float s = 0.0f; int f = 0;
            #pragma unroll
            for (int k = 0; k < K_; k++)
                if (ids[k] == e) { s += w[k]; f = 1; }
            g_comb[i * E_ + e] = s;
            g_flag[i * E_ + e] = f;
        }
    }
}

__global__ void route_compact_par() {
    __shared__ int s[T_];
    const int e = blockIdx.x;
    const int t = threadIdx.x;
    int f = g_flag[t * E_ + e];
    s[t] = f;
    __syncthreads();
    #pragma unroll
    for (int off = 1; off < T_; off <<= 1) {
        int v = (t >= off) ? s[t - off] : 0;
        __syncthreads();
        s[t] += v;
        __syncthreads();
    }
    if (f) g_tok[e * T_ + s[t] - 1] = t;
    if (t == T_ - 1) g_cnt[e] = s[t];
}

// fp4 byte -> packed bf16x2 / f16x2, scaled
__device__ __forceinline__ uint32_t dq2(int w, float s, const float* tab) {
    float lo = tab[w & 15] * s;
    float hi = tab[(w >> 4) & 15] * s;
    __nv_bfloat162 h = __floats2bfloat162_rn(lo, hi);
    return *reinterpret_cast<uint32_t*>(&h);
}
__device__ __forceinline__ uint32_t dq2h(int w, float s, const float* tab) {
    float lo = tab[w & 15] * s;
    float hi = tab[(w >> 4) & 15] * s;
    __half2 h = __floats2half2_rn(lo, hi);
    return *reinterpret_cast<uint32_t*>(&h);
}
__device__ __forceinline__ uint4 dq8(int4 w, float s, const float* tab) {
    uint4 o;
    o.x = dq2(w.x, s, tab); o.y = dq2(w.y, s, tab);
    o.z = dq2(w.z, s, tab); o.w = dq2(w.w, s, tab);
    return o;
}
__device__ __forceinline__ uint4 dq8h(int4 w, float s, const float* tab) {
    uint4 o;
    o.x = dq2h(w.x, s, tab); o.y = dq2h(w.y, s, tab);
    o.z = dq2h(w.z, s, tab); o.w = dq2h(w.w, s, tab);
    return o;
}

#define RS2 80                 // 32 elems x 2B + 16B pad (conflict-free ldmatrix)
#define STG (256 * RS2)        // one stage: 256 smem rows (A 128 + B 128) = 20480 B

// ================= GEMM1: h = x @ w13^T, a = silu(g)*u =================
// 256 thr, tile m128 x (G64 + U64), BK=32, 2-stage ping-pong, warps 4m x 2n, warp 32m x (32G+32U)
__global__ void __launch_bounds__(256, 2)
gemm1_kernel(const int* __restrict__ w13, const int* __restrict__ w13s) {
    const int e = blockIdx.z;
    const int cnt = g_cnt[e];
    const int m0 = blockIdx.y * 128;
    if (m0 >= cnt) return;
    const int n0 = blockIdx.x * 64;

    __shared__ __align__(16) unsigned char sm[2 * STG];
    __shared__ float tab[16];
    __shared__ int toks[128];

    const int tid = threadIdx.x, wid = tid >> 5, lid = tid & 31;
    if (tid < 16) tab[tid] = c_fp4[tid];
    if (tid < 128) toks[tid] = g_tok[e * T_ + min(m0 + tid, cnt - 1)];
    __syncthreads();

    const int* we = w13 + (size_t)e * (2 * I_) * (D_ / 2);
    const int* se = w13s + (size_t)e * (2 * I_) * (D_ / 32);
    const uint32_t smB = smem_u32(sm);
    const int wm = wid & 3, wn = wid >> 2;

    // A loader: 128 rows x 32 elems; thread covers 2 consecutive 16B segs
    const int car = tid >> 1, cas = (tid & 1) * 2;
    const size_t asrc = (size_t)toks[car] * D_ + cas * 8;
    const uint32_t adst = car * RS2 + cas * 16;
    // B loader: 128 rows (G 0-63, U 64-127), thread covers 2 int4 (16 elems)
    const int brow = tid >> 1, bseg = (tid & 1) * 2;
    const int bf = (brow < 64) ? (n0 + brow) : (I_ + n0 + brow - 64);
    const size_t bw = (size_t)bf * (D_ / 2) + bseg * 4;
    const size_t bs = (size_t)bf * (D_ / 32);
    const uint32_t bdst = (128 + brow) * RS2 + bseg * 16;

    float cg[2][4][4] = {};
    float cu[2][4][4] = {};

    uint4 pa[2]; int4 pw[2]; float ps;
    // chunk 0 -> stage 0
    pa[0] = *(const uint4*)&g_xb[asrc];
    pa[1] = *(const uint4*)&g_xb[asrc + 8];
    pw[0] = *(const int4*)&we[bw];
    pw[1] = *(const int4*)&we[bw + 4];
    ps = __uint_as_float((unsigned)se[bs] << 23);
    *(uint4*)(sm + adst) = pa[0];
    *(uint4*)(sm + adst + 16) = pa[1];
    *(uint4*)(sm + bdst) = dq8(pw[0], ps, tab);
    *(uint4*)(sm + bdst + 16) = dq8(pw[1], ps, tab);
    // prefetch chunk 1
    pa[0] = *(const uint4*)&g_xb[asrc + 32];
    pa[1] = *(const uint4*)&g_xb[asrc + 40];
    pw[0] = *(const int4*)&we[bw + 16];
    pw[1] = *(const int4*)&we[bw + 20];
    ps = __uint_as_float((unsigned)se[bs + 1] << 23);
    __syncthreads();

    const int NC = D_ / 32;
    for (int c = 0; c < NC; c++) {
        const uint32_t sb = smB + (c & 1) * STG;
        #pragma unroll
        for (int kk = 0; kk < 2; kk++) {
            uint32_t af[2][4];
            #pragma unroll
            for (int mf = 0; mf < 2; mf++)
                ldm_x4(af[mf], sb + (wm * 32 + mf * 16 + (lid & 15)) * RS2 + kk * 32 + (lid >> 4) * 16);
            const int nrow_off = ((lid >> 4) << 3) + (lid & 7);
            const int bcol = kk * 32 + ((lid >> 3) & 1) * 16;
            uint32_t bg[2][4], bu[2][4];
            #pragma unroll
            for (int ng = 0; ng < 2; ng++) {
                int nr = wn * 32 + ng * 16 + nrow_off;
                ldm_x4(bg[ng], sb + (128 + nr) * RS2 + bcol);
                ldm_x4(bu[ng], sb + (192 + nr) * RS2 + bcol);
            }
            #pragma unroll
            for (int mf = 0; mf < 2; mf++)
                #pragma unroll
                for (int ng = 0; ng < 2; ng++)
                    #pragma unroll
                    for (int sub = 0; sub < 2; sub++) {
                        mma_bf16(cg[mf][ng * 2 + sub], af[mf], &bg[ng][sub * 2]);
                        mma_bf16(cu[mf][ng * 2 + sub], af[mf], &bu[ng][sub * 2]);
                    }
        }
        // store prefetched chunk c+1 into other stage (its readers passed the previous barrier)
        if (c + 1 < NC) {
            unsigned char* so = sm + ((c + 1) & 1) * STG;
            *(uint4*)(so + adst) = pa[0];
            *(uint4*)(so + adst + 16) = pa[1];
            *(uint4*)(so + bdst) = dq8(pw[0], ps, tab);
            *(uint4*)(so + bdst + 16) = dq8(pw[1], ps, tab);
        }
        __syncthreads();
        // prefetch chunk c+2 (latency covered by next chunk's MMA phase)
        if (c + 2 < NC) {
            const int k0 = (c + 2) * 32;
            pa[0] = *(const uint4*)&g_xb[asrc + k0];
            pa[1] = *(const uint4*)&g_xb[asrc + k0 + 8];
            pw[0] = *(const int4*)&we[bw + (k0 >> 1)];
            pw[1] = *(const int4*)&we[bw + (k0 >> 1) + 4];
            ps = __uint_as_float((unsigned)se[bs + (k0 >> 5)] << 23);
        }
    }

    // epilogue: a = silu(g)*u, store a/64 as fp16
    #pragma unroll
    for (int mf = 0; mf < 2; mf++) {
        const int rbase = wm * 32 + mf * 16 + (lid >> 2);
        #pragma unroll
        for (int half = 0; half < 2; half++) {
            int m = m0 + rbase + half * 8;
            if (m < cnt) {
                size_t rowp = ((size_t)e * T_ + m) * I_ + n0;
                #pragma unroll
                for (int nf = 0; nf < 4; nf++) {
                    float g0 = cg[mf][nf][half * 2 + 0], g1 = cg[mf][nf][half * 2 + 1];
                    float u0 = cu[mf][nf][half * 2 + 0], u1 = cu[mf][nf][half * 2 + 1];
                    float a0 = g0 * u0 / (1.0f + __expf(-g0)) * 0.015625f;
                    float a1 = g1 * u1 / (1.0f + __expf(-g1)) * 0.015625f;
                    int col = wn * 32 + nf * 8 + (lid & 3) * 2;
                    __half2 h2 = __floats2half2_rn(a0, a1);
                    *(uint32_t*)&g_ah[rowp + col] = *(uint32_t*)&h2;
                }
            }
        }
    }
}

// ================= GEMM2: out += (64*comb) * ((a/64) @ w2^T) =================
// 256 thr, tile m128 x n128, BK=32, 2-stage ping-pong, warps 4m x 2n, warp 32 x 64
__global__ void __launch_bounds__(256, 2)
gemm2_kernel(const int* __restrict__ w2, const int* __restrict__ w2s, float* __restrict__ out) {
    const int e = blockIdx.z;
    const int cnt = g_cnt[e];
    const int m0 = blockIdx.y * 128;
    if (m0 >= cnt) return;
    const int n0 = blockIdx.x * 128;

    __shared__ __align__(16) unsigned char sm[2 * STG];
    __shared__ float tab[16];
    __shared__ int toks[128];

    const int tid = threadIdx.x, wid = tid >> 5, lid = tid & 31;
    if (tid < 16) tab[tid] = c_fp4[tid];
    if (tid < 128) toks[tid] = g_tok[e * T_ + min(m0 + tid, cnt - 1)];
    __syncthreads();

    const int* we = w2 + (size_t)e * D_ * (I_ / 2);
    const int* se = w2s + (size_t)e * D_ * (I_ / 32);
    const uint32_t smB = smem_u32(sm);
    const int wm = wid & 3, wn = wid >> 2;

    const int car = tid >> 1, cas = (tid & 1) * 2;
    const size_t asrc = ((size_t)e * T_ + m0 + car) * I_ + cas * 8;
    const uint32_t adst = car * RS2 + cas * 16;
    const int brow = tid >> 1, bseg = (tid & 1) * 2;
    const int bf = n0 + brow;
    const size_t bw = (size_t)bf * (I_ / 2) + bseg * 4;
    const size_t bs = (size_t)bf * (I_ / 32);
    const uint32_t bdst = (128 + brow) * RS2 + bseg * 16;

    float acc[2][8][4] = {};

    uint4 pa[2]; int4 pw[2]; float ps;
    pa[0] = *(const uint4*)&g_ah[asrc];
    pa[1] = *(const uint4*)&g_ah[asrc + 8];
    pw[0] = *(const int4*)&we[bw];
    pw[1] = *(const int4*)&we[bw + 4];
    ps = __uint_as_float((unsigned)se[bs] << 23);
    *(uint4*)(sm + adst) = pa[0];
    *(uint4*)(sm + adst + 16) = pa[1];
    *(uint4*)(sm + bdst) = dq8h(pw[0], ps, tab);
    *(uint4*)(sm + bdst + 16) = dq8h(pw[1], ps, tab);
    pa[0] = *(const uint4*)&g_ah[asrc + 32];
    pa[1] = *(const uint4*)&g_ah[asrc + 40];
    pw[0] = *(const int4*)&we[bw + 16];
    pw[1] = *(const int4*)&we[bw + 20];
    ps = __uint_as_float((unsigned)se[bs + 1] << 23);
    __syncthreads();

    const int NC = I_ / 32;
    for (int c = 0; c < NC; c++) {
        const uint32_t sb = smB + (c & 1) * STG;
        #pragma unroll
        for (int kk = 0; kk < 2; kk++) {
            uint32_t af[2][4];
            #pragma unroll
            for (int mf = 0; mf < 2; mf++)
                ldm_x4(af[mf], sb + (wm * 32 + mf * 16 + (lid & 15)) * RS2 + kk * 32 + (lid >> 4) * 16);
            const int nrow_off = ((lid >> 4) << 3) + (lid & 7);
            const int bcol = kk * 32 + ((lid >> 3) & 1) * 16;
            #pragma unroll
            for (int hn = 0; hn < 2; hn++) {
                uint32_t bb[2][4];
                #pragma unroll
                for (int ng = 0; ng < 2; ng++) {
                    int nr = wn * 64 + (hn * 2 + ng) * 16 + nrow_off;
                    ldm_x4(bb[ng], sb + (128 + nr) * RS2 + bcol);
                }
                #pragma unroll
                for (int mf = 0; mf < 2; mf++)
                    #pragma unroll
                    for (int ng = 0; ng < 2; ng++)
                        #pragma unroll
                        for (int sub = 0; sub < 2; sub++)
                            mma_f16(acc[mf][(hn * 2 + ng) * 2 + sub], af[mf], &bb[ng][sub * 2]);
            }
        }
        if (c + 1 < NC) {
            unsigned char* so = sm + ((c + 1) & 1) * STG;
            *(uint4*)(so + adst) = pa[0];
            *(uint4*)(so + adst + 16) = pa[1];
            *(uint4*)(so + bdst) = dq8h(pw[0], ps, tab);
            *(uint4*)(so + bdst + 16) = dq8h(pw[1], ps, tab);
        }
        __syncthreads();
        if (c + 2 < NC) {
            const int k0 = (c + 2) * 32;
            pa[0] = *(const uint4*)&g_ah[asrc + k0];
            pa[1] = *(const uint4*)&g_ah[asrc + k0 + 8];
            pw[0] = *(const int4*)&we[bw + (k0 >> 1)];
            pw[1] = *(const int4*)&we[bw + (k0 >> 1) + 4];
            ps = __uint_as_float((unsigned)se[bs + (k0 >> 5)] << 23);
        }
    }

    // epilogue: weighted scatter (comb * 64 compensates a/64)
    #pragma unroll
    for (int mf = 0; mf < 2; mf++) {
        const int rbase = wm * 32 + mf * 16 + (lid >> 2);
        #pragma unroll
        for (int half = 0; half < 2; half++) {
            int mrow = rbase + half * 8;
            int m = m0 + mrow;
            if (m < cnt) {
                int t = toks[mrow];
                float cw = g_comb[t * E_ + e] * 64.0f;
                float* orow = out + (size_t)t * D_ + n0;
                #pragma unroll
                for (int nf = 0; nf < 8; nf++) {
                    int col = wn * 64 + nf * 8 + (lid & 3) * 2;
                    atomicAdd(&orow[col],     cw * acc[mf][nf][half * 2 + 0]);
                    atomicAdd(&orow[col + 1], cw * acc[mf][nf][half * 2 + 1]);
                }
            }
        }
    }
}

// ---------------- launch ----------------
extern "C" void kernel_launch(void* const* d_in, const int* in_sizes, int n_in,
                              void* d_out, int out_size) {
    const float* hs   = (const float*)d_in[0];
    const float* tw   = (const float*)d_in[1];
    const int*   tids = (const int*)d_in[2];
    const int*   w13  = (const int*)d_in[3];
    const int*   w13s = (const int*)d_in[4];
    const int*   w2   = (const int*)d_in[5];
    const int*   w2s  = (const int*)d_in[6];
    float* out = (float*)d_out;

    prep_kernel<<<(T_ * D_ + 255) / 256, 256>>>(hs, tw, tids, out);
    route_compact_par<<<E_, T_>>>();

    dim3 g1(I_ / 64, T_ / 128, E_);    // 12 x 4 x 16
    gemm1_kernel<<<g1, 256>>>(w13, w13s);

    dim3 g2(D_ / 128, T_ / 128, E_);   // 16 x 4 x 16
    gemm2_kernel<<<g2, 256>>>(w2, w2s, out);
}

// round 12
// speedup vs baseline: 1.4060x; 1.3410x over previous
#include <cuda_runtime.h>
#include <cuda_bf16.h>
#include <cuda_fp16.h>
#include <cuda_fp8.h>
#include <math.h>
#include <stdint.h>

#define T_ 512
#define D_ 2048
#define I_ 768
#define E_ 16
#define K_ 8

// ---------------- helpers ----------------
__device__ __forceinline__ uint32_t smem_u32(const void* p) {
    uint32_t a;
    asm("{ .reg .u64 t; cvta.to.shared.u64 t, %1; cvt.u32.u64 %0, t; }" : "=r"(a) : "l"(p));
    return a;
}
__device__ __forceinline__ void ldm_x4(uint32_t* r, uint32_t addr) {
    asm volatile("ldmatrix.sync.aligned.m8n8.x4.shared.b16 {%0,%1,%2,%3}, [%4];"
        : "=r"(r[0]), "=r"(r[1]), "=r"(r[2]), "=r"(r[3]) : "r"(addr));
}
__device__ __forceinline__ void mma_bf16(float* c, const uint32_t* a, const uint32_t* b) {
    asm volatile("mma.sync.aligned.m16n8k16.row.col.f32.bf16.bf16.f32 "
        "{%0,%1,%2,%3}, {%4,%5,%6,%7}, {%8,%9}, {%0,%1,%2,%3};"
        : "+f"(c[0]), "+f"(c[1]), "+f"(c[2]), "+f"(c[3])
        : "r"(a[0]), "r"(a[1]), "r"(a[2]), "r"(a[3]), "r"(b[0]), "r"(b[1]));
}
__device__ __forceinline__ void mma_f16(float* c, const uint32_t* a, const uint32_t* b) {
    asm volatile("mma.sync.aligned.m16n8k16.row.col.f32.f16.f16.f32 "
        "{%0,%1,%2,%3}, {%4,%5,%6,%7}, {%8,%9}, {%0,%1,%2,%3};"
        : "+f"(c[0]), "+f"(c[1]), "+f"(c[2]), "+f"(c[3])
        : "r"(a[0]), "r"(a[1]), "r"(a[2]), "r"(a[3]), "r"(b[0]), "r"(b[1]));
}

// ---------------- scratch ----------------
__device__ __nv_bfloat16 g_xb[T_ * D_];   // quant-dequantized activations (exact bf16)
__device__ __half g_ah[E_ * T_ * I_];     // activation a/64 in fp16
__device__ int   g_tok[E_ * T_];
__device__ int   g_cnt[E_];
__device__ float g_comb[T_ * E_];
__device__ int   g_flag[T_ * E_];

__constant__ float c_fp4[16] = {0.0f, 0.5f, 1.0f, 1.5f, 2.0f, 3.0f, 4.0f, 6.0f,
                                -0.0f, -0.5f, -1.0f, -1.5f, -2.0f, -3.0f, -4.0f, -6.0f};

// ---------------- fused preamble ----------------
__global__ void prep_kernel(const float* __restrict__ x,
                            const float* __restrict__ tw,
                            const int* __restrict__ tids,
                            float* __restrict__ out) {
    const int i = blockIdx.x * blockDim.x + threadIdx.x;
    if (i < T_ * D_) out[i] = 0.0f;

    {
        int g = i >> 5, lane = i & 31;
        if (g < (T_ * D_) / 32) {
            float v = x[g * 32 + lane];
            float av = fabsf(v);
            #pragma unroll
            for (int o = 16; o; o >>= 1) av = fmaxf(av, __shfl_xor_sync(0xffffffffu, av, o));
            av = fmaxf(av, 1e-4f);
            float scale = av / 448.0f;
            unsigned bits = __float_as_uint(scale);
            unsigned exp = ((bits >> 23) & 255u) + ((bits & 0x7fffffu) ? 1u : 0u);
            exp = min(max(exp, 1u), 254u);
            float rscale = __uint_as_float(exp << 23);
            float inv = 1.0f / rscale;
            __nv_fp8_storage_t q = __nv_cvt_float_to_fp8(v * inv, __NV_SATFINITE, __NV_E4M3);
            float qf = __half2float(__half(__nv_cvt_fp8_to_halfraw(q, __NV_E4M3)));
            g_xb[g * 32 + lane] = __float2bfloat16(qf * rscale);
        }
    }

    if (i < T_) {
        int ids[K_]; float w[K_];
        #pragma unroll
        for (int k = 0; k < K_; k++) { ids[k] = tids[i * K_ + k]; w[k] = tw[i * K_ + k]; }
        #pragma unroll
        for (int e = 0; e < E_; e++) {
            float s = 0.0f; int f = 0;
            #pragma unroll
            for (int k = 0; k < K_; k++)
                if (ids[k] == e) { s += w[k]; f = 1; }
            g_comb[i * E_ + e] = s;
            g_flag[i * E_ + e] = f;
        }
    }
}

__global__ void route_compact_par() {
    __shared__ int s[T_];
    const int e = blockIdx.x;
    const int t = threadIdx.x;
    int f = g_flag[t * E_ + e];
    s[t] = f;
    __syncthreads();
    #pragma unroll
    for (int off = 1; off < T_; off <<= 1) {
        int v = (t >= off) ? s[t - off] : 0;
        __syncthreads();
        s[t] += v;
        __syncthreads();
    }
    if (f) g_tok[e * T_ + s[t] - 1] = t;
    if (t == T_ - 1) g_cnt[e] = s[t];
}

// fp4 byte -> packed bf16x2 / f16x2, scaled
__device__ __forceinline__ uint32_t dq2(int w, float s, const float* tab) {
    float lo = tab[w & 15] * s;
    float hi = tab[(w >> 4) & 15] * s;
    __nv_bfloat162 h = __floats2bfloat162_rn(lo, hi);
    return *reinterpret_cast<uint32_t*>(&h);
}
__device__ __forceinline__ uint32_t dq2h(int w, float s, const float* tab) {
    float lo = tab[w & 15] * s;
    float hi = tab[(w >> 4) & 15] * s;
    __half2 h = __floats2half2_rn(lo, hi);
    return *reinterpret_cast<uint32_t*>(&h);
}
__device__ __forceinline__ uint4 dq8(int4 w, float s, const float* tab) {
    uint4 o;
    o.x = dq2(w.x, s, tab); o.y = dq2(w.y, s, tab);
    o.z = dq2(w.z, s, tab); o.w = dq2(w.w, s, tab);
    return o;
}
__device__ __forceinline__ uint4 dq8h(int4 w, float s, const float* tab) {
    uint4 o;
    o.x = dq2h(w.x, s, tab); o.y = dq2h(w.y, s, tab);
    o.z = dq2h(w.z, s, tab); o.w = dq2h(w.w, s, tab);
    return o;
}

#define RSX 144                 // 64 elems x 2B + 16B pad (conflict-free ldmatrix)
#define STGX (256 * RSX)        // one stage: 256 smem rows (A 128 + B 128) = 36864 B
#define DYN_SMEM (2 * STGX)     // 73728 B dynamic

// ================= GEMM1: h = x @ w13^T, a = silu(g)*u  (bf16, BK=64 double-buffer) =================
// 256 thr, tile m128 x (G64 + U64); warps 4m x 2n; warp 32m x (32G + 32U)
__global__ void __launch_bounds__(256, 2)
gemm1_kernel(const int* __restrict__ w13, const int* __restrict__ w13s) {
    const int e = blockIdx.z;
    const int cnt = g_cnt[e];
    const int m0 = blockIdx.y * 128;
    if (m0 >= cnt) return;
    const int n0 = blockIdx.x * 64;

    extern __shared__ __align__(16) unsigned char dsm[];
    __shared__ float tab[16];
    __shared__ int toks[128];

    const int tid = threadIdx.x, wid = tid >> 5, lid = tid & 31;
    if (tid < 16) tab[tid] = c_fp4[tid];
    if (tid < 128) toks[tid] = g_tok[e * T_ + min(m0 + tid, cnt - 1)];
    __syncthreads();

    const int* we = w13 + (size_t)e * (2 * I_) * (D_ / 2);
    const int* se = w13s + (size_t)e * (2 * I_) * (D_ / 32);
    const uint32_t smB = smem_u32(dsm);
    const int wm = wid & 3, wn = wid >> 2;

    // per-thread fixed load coordinates (champion mapping, fully coalesced)
    int arow[4], aseg[4];
    int brow[4], bseg[4], bfeat[4];
    uint32_t bhalf[4];
    #pragma unroll
    for (int r = 0; r < 4; r++) {
        int j = tid + r * 256;
        arow[r] = j >> 3; aseg[r] = j & 7;
        int half = j >> 9, jj = j & 511;
        brow[r] = jj >> 3; bseg[r] = jj & 7;
        bfeat[r] = n0 + brow[r] + half * I_;
        bhalf[r] = half;
    }

    float cg[2][4][4] = {};
    float cu[2][4][4] = {};

    uint4 pa[4]; int4 pw[4]; float ps[4];
    // LDG chunk 0
    #pragma unroll
    for (int r = 0; r < 4; r++) {
        pa[r] = *(const uint4*)&g_xb[(size_t)toks[arow[r]] * D_ + aseg[r] * 8];
        ps[r] = __uint_as_float((unsigned)se[(size_t)bfeat[r] * (D_ / 32) + (bseg[r] >> 2)] << 23);
        pw[r] = *(const int4*)&we[(size_t)bfeat[r] * (D_ / 2) + bseg[r] * 4];
    }
    // STS chunk 0 -> stage 0
    #pragma unroll
    for (int r = 0; r < 4; r++) {
        *(uint4*)(dsm + arow[r] * RSX + aseg[r] * 16) = pa[r];
        *(uint4*)(dsm + (128 + bhalf[r] * 64 + brow[r]) * RSX + bseg[r] * 16) = dq8(pw[r], ps[r], tab);
    }
    // LDG chunk 1
    #pragma unroll
    for (int r = 0; r < 4; r++) {
        pa[r] = *(const uint4*)&g_xb[(size_t)toks[arow[r]] * D_ + 64 + aseg[r] * 8];
        ps[r] = __uint_as_float((unsigned)se[(size_t)bfeat[r] * (D_ / 32) + 2 + (bseg[r] >> 2)] << 23);
        pw[r] = *(const int4*)&we[(size_t)bfeat[r] * (D_ / 2) + 32 + bseg[r] * 4];
    }
    __syncthreads();

    const int NC = D_ / 64;
    for (int c = 0; c < NC; c++) {
        const uint32_t sb = smB + (c & 1) * STGX;
        // MMA on stage c&1 (champion inner loop)
        #pragma unroll
        for (int kk = 0; kk < 4; kk++) {
            uint32_t af[2][4];
            #pragma unroll
            for (int mf = 0; mf < 2; mf++)
                ldm_x4(af[mf], sb + (wm * 32 + mf * 16 + (lid & 15)) * RSX + kk * 32 + (lid >> 4) * 16);
            const int nrow_off = ((lid >> 4) << 3) + (lid & 7);
            const int bcol = kk * 32 + ((lid >> 3) & 1) * 16;
            uint32_t bg[2][4], bu[2][4];
            #pragma unroll
            for (int ng = 0; ng < 2; ng++) {
                int nr = wn * 32 + ng * 16 + nrow_off;
                ldm_x4(bg[ng], sb + (128 + nr) * RSX + bcol);
                ldm_x4(bu[ng], sb + (192 + nr) * RSX + bcol);
            }
            #pragma unroll
            for (int mf = 0; mf < 2; mf++)
                #pragma unroll
                for (int ng = 0; ng < 2; ng++)
                    #pragma unroll
                    for (int sub = 0; sub < 2; sub++) {
                        mma_bf16(cg[mf][ng * 2 + sub], af[mf], &bg[ng][sub * 2]);
                        mma_bf16(cu[mf][ng * 2 + sub], af[mf], &bu[ng][sub * 2]);
                    }
        }
        // STS chunk c+1 -> stage (c+1)&1 (its readers finished MMA(c-1) before last barrier)
        if (c + 1 < NC) {
            unsigned char* so = dsm + ((c + 1) & 1) * STGX;
            #pragma unroll
            for (int r = 0; r < 4; r++) {
                *(uint4*)(so + arow[r] * RSX + aseg[r] * 16) = pa[r];
                *(uint4*)(so + (128 + bhalf[r] * 64 + brow[r]) * RSX + bseg[r] * 16) = dq8(pw[r], ps[r], tab);
            }
        }
        __syncthreads();
        // LDG chunk c+2 (latency window = full MMA phase of chunk c+1)
        if (c + 2 < NC) {
            const int k0 = (c + 2) * 64;
            #pragma unroll
            for (int r = 0; r < 4; r++) {
                pa[r] = *(const uint4*)&g_xb[(size_t)toks[arow[r]] * D_ + k0 + aseg[r] * 8];
                ps[r] = __uint_as_float((unsigned)se[(size_t)bfeat[r] * (D_ / 32) + (k0 >> 5) + (bseg[r] >> 2)] << 23);
                pw[r] = *(const int4*)&we[(size_t)bfeat[r] * (D_ / 2) + (k0 >> 1) + bseg[r] * 4];
            }
        }
    }

    // epilogue: a = silu(g)*u, store a/64 as fp16 (champion verbatim)
    #pragma unroll
    for (int mf = 0; mf < 2; mf++) {
        const int rbase = wm * 32 + mf * 16 + (lid >> 2);
        #pragma unroll
        for (int half = 0; half < 2; half++) {
            int m = m0 + rbase + half * 8;
            if (m < cnt) {
                size_t rowp = ((size_t)e * T_ + m) * I_ + n0;
                #pragma unroll
                for (int nf = 0; nf < 4; nf++) {
                    float g0 = cg[mf][nf][half * 2 + 0], g1 = cg[mf][nf][half * 2 + 1];
                    float u0 = cu[mf][nf][half * 2 + 0], u1 = cu[mf][nf][half * 2 + 1];
                    float a0 = g0 * u0 / (1.0f + __expf(-g0)) * 0.015625f;
                    float a1 = g1 * u1 / (1.0f + __expf(-g1)) * 0.015625f;
                    int col = wn * 32 + nf * 8 + (lid & 3) * 2;
                    __half2 h2 = __floats2half2_rn(a0, a1);
                    *(uint32_t*)&g_ah[rowp + col] = *(uint32_t*)&h2;
                }
            }
        }
    }
}

// ================= GEMM2: out += (64*comb) * ((a/64) @ w2^T)  (fp16, BK=64 double-buffer) =================
// 256 thr, tile m128 x n128; warps 4m x 2n; warp 32 x 64
__global__ void __launch_bounds__(256, 2)
gemm2_kernel(const int* __restrict__ w2, const int* __restrict__ w2s, float* __restrict__ out) {
    const int e = blockIdx.z;
    const int cnt = g_cnt[e];
    const int m0 = blockIdx.y * 128;
    if (m0 >= cnt) return;
    const int n0 = blockIdx.x * 128;

    extern __shared__ __align__(16) unsigned char dsm[];
    __shared__ float tab[16];
    __shared__ int toks[128];

    const int tid = threadIdx.x, wid = tid >> 5, lid = tid & 31;
    if (tid < 16) tab[tid] = c_fp4[tid];
    if (tid < 128) toks[tid] = g_tok[e * T_ + min(m0 + tid, cnt - 1)];
    __syncthreads();

    const int* we = w2 + (size_t)e * D_ * (I_ / 2);
    const int* se = w2s + (size_t)e * D_ * (I_ / 32);
    const uint32_t smB = smem_u32(dsm);
    const int wm = wid & 3, wn = wid >> 2;

    int row_[4], seg_[4];
    #pragma unroll
    for (int r = 0; r < 4; r++) {
        int j = tid + r * 256;
        row_[r] = j >> 3; seg_[r] = j & 7;
    }

    float acc[2][8][4] = {};

    uint4 pa[4]; int4 pw[4]; float ps[4];
    // LDG chunk 0
    #pragma unroll
    for (int r = 0; r < 4; r++) {
        pa[r] = *(const uint4*)&g_ah[((size_t)e * T_ + m0 + row_[r]) * I_ + seg_[r] * 8];
        int f = n0 + row_[r];
        ps[r] = __uint_as_float((unsigned)se[(size_t)f * (I_ / 32) + (seg_[r] >> 2)] << 23);
        pw[r] = *(const int4*)&we[(size_t)f * (I_ / 2) + seg_[r] * 4];
    }
    // STS chunk 0 -> stage 0
    #pragma unroll
    for (int r = 0; r < 4; r++) {
        *(uint4*)(dsm + row_[r] * RSX + seg_[r] * 16) = pa[r];
        *(uint4*)(dsm + (128 + row_[r]) * RSX + seg_[r] * 16) = dq8h(pw[r], ps[r], tab);
    }
    // LDG chunk 1
    #pragma unroll
    for (int r = 0; r < 4; r++) {
        pa[r] = *(const uint4*)&g_ah[((size_t)e * T_ + m0 + row_[r]) * I_ + 64 + seg_[r] * 8];
        int f = n0 + row_[r];
        ps[r] = __uint_as_float((unsigned)se[(size_t)f * (I_ / 32) + 2 + (seg_[r] >> 2)] << 23);
        pw[r] = *(const int4*)&we[(size_t)f * (I_ / 2) + 32 + seg_[r] * 4];
    }
    __syncthreads();

    const int NC = I_ / 64;
    for (int c = 0; c < NC; c++) {
        const uint32_t sb = smB + (c & 1) * STGX;
        #pragma unroll
        for (int kk = 0; kk < 4; kk++) {
            uint32_t af[2][4];
            #pragma unroll
            for (int mf = 0; mf < 2; mf++)
                ldm_x4(af[mf], sb + (wm * 32 + mf * 16 + (lid & 15)) * RSX + kk * 32 + (lid >> 4) * 16);
            const int nrow_off = ((lid >> 4) << 3) + (lid & 7);
            const int bcol = kk * 32 + ((lid >> 3) & 1) * 16;
            #pragma unroll
            for (int hn = 0; hn < 2; hn++) {
                uint32_t bb[2][4];
                #pragma unroll
                for (int ng = 0; ng < 2; ng++) {
                    int nr = wn * 64 + (hn * 2 + ng) * 16 + nrow_off;
                    ldm_x4(bb[ng], sb + (128 + nr) * RSX + bcol);
                }
                #pragma unroll
                for (int mf = 0; mf < 2; mf++)
                    #pragma unroll
                    for (int ng = 0; ng < 2; ng++)
                        #pragma unroll
                        for (int sub = 0; sub < 2; sub++)
                            mma_f16(acc[mf][(hn * 2 + ng) * 2 + sub], af[mf], &bb[ng][sub * 2]);
            }
        }
        if (c + 1 < NC) {
            unsigned char* so = dsm + ((c + 1) & 1) * STGX;
            #pragma unroll
            for (int r = 0; r < 4; r++) {
                *(uint4*)(so + row_[r] * RSX + seg_[r] * 16) = pa[r];
                *(uint4*)(so + (128 + row_[r]) * RSX + seg_[r] * 16) = dq8h(pw[r], ps[r], tab);
            }
        }
        __syncthreads();
        if (c + 2 < NC) {
            const int k0 = (c + 2) * 64;
            #pragma unroll
            for (int r = 0; r < 4; r++) {
                pa[r] = *(const uint4*)&g_ah[((size_t)e * T_ + m0 + row_[r]) * I_ + k0 + seg_[r] * 8];
                int f = n0 + row_[r];
                ps[r] = __uint_as_float((unsigned)se[(size_t)f * (I_ / 32) + (k0 >> 5) + (seg_[r] >> 2)] << 23);
                pw[r] = *(const int4*)&we[(size_t)f * (I_ / 2) + (k0 >> 1) + seg_[r] * 4];
            }
        }
    }

    // epilogue: weighted scatter (comb * 64 compensates a/64) — champion verbatim
    #pragma unroll
    for (int mf = 0; mf < 2; mf++) {
        const int rbase = wm * 32 + mf * 16 + (lid >> 2);
        #pragma unroll
        for (int half = 0; half < 2; half++) {
            int mrow = rbase + half * 8;
            int m = m0 + mrow;
            if (m < cnt) {
                int t = toks[mrow];
                float cw = g_comb[t * E_ + e] * 64.0f;
                float* orow = out + (size_t)t * D_ + n0;
                #pragma unroll
                for (int nf = 0; nf < 8; nf++) {
                    int col = wn * 64 + nf * 8 + (lid & 3) * 2;
                    atomicAdd(&orow[col],     cw * acc[mf][nf][half * 2 + 0]);
                    atomicAdd(&orow[col + 1], cw * acc[mf][nf][half * 2 + 1]);
                }
            }
        }
    }
}

// ---------------- launch ----------------
extern "C" void kernel_launch(void* const* d_in, const int* in_sizes, int n_in,
                              void* d_out, int out_size) {
    const float* hs   = (const float*)d_in[0];
    const float* tw   = (const float*)d_in[1];
    const int*   tids = (const int*)d_in[2];
    const int*   w13  = (const int*)d_in[3];
    const int*   w13s = (const int*)d_in[4];
    const int*   w2   = (const int*)d_in[5];
    const int*   w2s  = (const int*)d_in[6];
    float* out = (float*)d_out;

    // attribute persists per-function; set every call, ignore result (first,
    // uncaptured call establishes it — not a stream op, capture-neutral)
    cudaFuncSetAttribute(gemm1_kernel, cudaFuncAttributeMaxDynamicSharedMemorySize, DYN_SMEM);
    cudaFuncSetAttribute(gemm2_kernel, cudaFuncAttributeMaxDynamicSharedMemorySize, DYN_SMEM);

    prep_kernel<<<(T_ * D_ + 255) / 256, 256>>>(hs, tw, tids, out);
    route_compact_par<<<E_, T_>>>();

    dim3 g1(I_ / 64, T_ / 128, E_);    // 12 x 4 x 16
    gemm1_kernel<<<g1, 256, DYN_SMEM>>>(w13, w13s);

    dim3 g2(D_ / 128, T_ / 128, E_);   // 16 x 4 x 16
    gemm2_kernel<<<g2, 256, DYN_SMEM>>>(w2, w2s, out);
}